// round 17
// baseline (speedup 1.0000x reference)
#include <cuda_runtime.h>

// LbpBlock: out = concat([x, pad(x_cat)], ch axis)
//   y[n,o,h,w] = sum_c x[n,c,h,w]*conv_w[o,c]   (c=3, o=64)
//   x_cat interior = sum_l H(y_c - y_shift_l) * exp(w[o,l]), zero border.
// x: (8,3,256,256) f32, conv_w: (64,3), w: (64,8) -> out: (8,67,256,256)
//
// R17 = R16 shared-edge structure with predication-friendly codegen:
// every conditional accumulate is an if/else on the shared-edge bool so
// ptxas emits FSETP + @P FADD + @!P FADD (no FSEL). Per shared edge per
// channel: 3 instr (R12: 4, R16: 5).

#define NN   8
#define CIN  3
#define HH   256
#define WW   256
#define TH   32
#define TW   64
#define NT   256
#define HALO_H 34
#define HALO_W 66
#define CP   74                    // swizzled f4 row pitch (sw(65)=73)
#define PLANE (HH * WW)
#define NF4  544                   // interior f4 slots: 34 rows x 16
#define NSLOT (NF4 + 68)           // + scalar edge slots (34 rows x 2)

struct Sm {
    float4 sy[2][HALO_H][CP];      // 80512 B: y for both chunks (8 ch)
    float2 sewp[4][8];             // exp(w) for this block's 4 channel pairs
};                                  // 80768 B -> 2 CTAs/SM

__device__ __forceinline__ int sw(int c) { return c + (c >> 3); }

__global__ __launch_bounds__(NT, 2)
void lbp_main(const float* __restrict__ x,
              const float* __restrict__ cw,
              const float* __restrict__ w,
              float* __restrict__ out)
{
    extern __shared__ unsigned char raw[];
    Sm* sm = (Sm*)raw;

    const int tid = threadIdx.x;
    const int bz  = blockIdx.z;
    const int n   = bz >> 3;          // image
    const int cg  = bz & 7;           // channel group (8 ch)
    const int o0  = 8 * cg;
    const int h0  = blockIdx.y * TH;
    const int w0  = blockIdx.x * TW;

    // ---- exp(w) for this block's 4 channel pairs (32 expf total) ----
    if (tid < 32) {
        const int pi = tid >> 3, l = tid & 7;
        sm->sewp[pi][l] = make_float2(__expf(w[(o0 + 2 * pi) * 8 + l]),
                                      __expf(w[(o0 + 2 * pi + 1) * 8 + l]));
    }

    // ---- conv weights: 6 broadcast LDG.128 (24*cg % 4 == 0 -> aligned) ----
    const float4* cw4 = (const float4*)(cw + 3 * o0);
    const float4 A0 = cw4[0], A1 = cw4[1], A2 = cw4[2];   // chunk 0 (4 ch)
    const float4 B0 = cw4[3], B1 = cw4[4], B2 = cw4[5];   // chunk 1 (4 ch)

    // ---- x halo -> registers, shift-only indexing ----
    float xs[3][3][4];                // [k][plane][px]
    int   rk[3], ck[3], tk[3];        // row, first halo col, type
    #pragma unroll
    for (int k = 0; k < 3; k++) {
        const int s = tid + k * NT;
        #pragma unroll
        for (int p = 0; p < 3; p++)
            #pragma unroll
            for (int i = 0; i < 4; i++)
                xs[k][p][i] = 0.f;
        if (s < NF4) {
            const int r = s >> 4, q = s & 15;
            rk[k] = r; ck[k] = 1 + 4 * q; tk[k] = 0;
            const int gh = h0 - 1 + r;
            if ((unsigned)gh < HH) {
                const int base = (n * CIN * HH + gh) * WW + (w0 + 4 * q);
                #pragma unroll
                for (int p = 0; p < 3; p++) {
                    const float4 t = *(const float4*)(x + base + p * PLANE);
                    xs[k][p][0] = t.x; xs[k][p][1] = t.y;
                    xs[k][p][2] = t.z; xs[k][p][3] = t.w;
                }
            }
        } else if (s < NSLOT) {
            const int e2 = s - NF4;
            const int r = e2 >> 1, side = e2 & 1;
            rk[k] = r; ck[k] = side ? 65 : 0; tk[k] = 1;
            const int gh = h0 - 1 + r;
            const int gw = w0 - 1 + ck[k];
            if ((unsigned)gh < HH && (unsigned)gw < WW) {
                const int base = (n * CIN * HH + gh) * WW + gw;
                #pragma unroll
                for (int p = 0; p < 3; p++)
                    xs[k][p][0] = x[base + p * PLANE];
            }
        } else {
            rk[k] = 0; ck[k] = 0; tk[k] = 2;
        }
    }

    // ---- distributed copy: every block copies 192 f4 of its tile ----
    if (tid < 192) {
        const float4* x4 = (const float4*)(x + n * CIN * PLANE);
        float4*       o4 = (float4*)(out + n * 67 * PLANE);
        const int f   = cg * 192 + tid;
        const int c   = f >> 9;
        const int rem = f & 511;
        const int rr  = rem >> 4;
        const int cc  = rem & 15;
        const int idx = c * (PLANE / 4) + (h0 + rr) * (WW / 4) + (w0 >> 2) + cc;
        o4[idx] = x4[idx];
    }

    // ---- fill BOTH chunks' y (register FMA -> STS.128) ----
    #pragma unroll
    for (int ch2 = 0; ch2 < 2; ch2++) {
        const float4 W0 = ch2 ? B0 : A0;
        const float4 W1 = ch2 ? B1 : A1;
        const float4 W2 = ch2 ? B2 : A2;
        #pragma unroll
        for (int k = 0; k < 3; k++) {
            if (tk[k] == 0) {
                #pragma unroll
                for (int i = 0; i < 4; i++) {
                    const float a = xs[k][0][i], b = xs[k][1][i], d = xs[k][2][i];
                    float4 v;
                    v.x = fmaf(d, W0.z, fmaf(b, W0.y, a * W0.x));
                    v.y = fmaf(d, W1.y, fmaf(b, W1.x, a * W0.w));
                    v.z = fmaf(d, W2.x, fmaf(b, W1.w, a * W1.z));
                    v.w = fmaf(d, W2.w, fmaf(b, W2.z, a * W2.y));
                    sm->sy[ch2][rk[k]][sw(ck[k] + i)] = v;
                }
            } else if (tk[k] == 1) {
                const float a = xs[k][0][0], b = xs[k][1][0], d = xs[k][2][0];
                float4 v;
                v.x = fmaf(d, W0.z, fmaf(b, W0.y, a * W0.x));
                v.y = fmaf(d, W1.y, fmaf(b, W1.x, a * W0.w));
                v.z = fmaf(d, W2.x, fmaf(b, W1.w, a * W1.z));
                v.w = fmaf(d, W2.w, fmaf(b, W2.z, a * W2.y));
                sm->sy[ch2][rk[k]][sw(ck[k])] = v;
            }
        }
    }
    __syncthreads();   // the ONLY barrier

    // ---- phase 2: 2 rows x 4 cols micro-tile, shared-edge comparisons ----
    const int mc  = tid & 15;            // col group (4 px)
    const int mrg = tid >> 4;            // row pair (0..15)
    const int hr0 = 2 * mrg;             // top window halo row
    const int sc0 = 4 * mc;              // window halo col base
    const int oh0 = h0 + 2 * mrg;
    const int owb = w0 + 4 * mc;

    float mk0[4], mk1[4];
    {
        const bool hv0 = ((unsigned)(oh0 - 1) < (unsigned)(HH - 2));
        const bool hv1 = ((unsigned)(oh0)     < (unsigned)(HH - 2));
        #pragma unroll
        for (int jj = 0; jj < 4; jj++) {
            const bool cmj = ((unsigned)(owb + jj - 1) < (unsigned)(WW - 2));
            mk0[jj] = (hv0 && cmj) ? 1.f : 0.f;
            mk1[jj] = (hv1 && cmj) ? 1.f : 0.f;
        }
    }
    float* const outB = out + (n * 67 + 3 + o0) * PLANE + owb;

    // ROW0: row0 partial acc = top-halo (l0,l1,l2) + horizontal L/R (l3,l7)
    // via 5 shared edges on M. All accumulates are @P FADD (no FSEL).
    #define ROW0(T, M, FX, FY, ep, tx, ty) {                              \
        const float2 E0 = ep[0], E1 = ep[1], E2 = ep[2];                  \
        const float2 E3 = ep[3], E7 = ep[7];                              \
        _Pragma("unroll")                                                 \
        for (int jj = 0; jj < 4; jj++) {                                  \
            const float cx = M[jj + 1].FX, cy = M[jj + 1].FY;             \
            float ax = 0.f, ay = 0.f;                                     \
            if (cx > T[jj    ].FX) ax += E0.x;                            \
            if (cy > T[jj    ].FY) ay += E0.y;                            \
            if (cx > T[jj + 1].FX) ax += E1.x;                            \
            if (cy > T[jj + 1].FY) ay += E1.y;                            \
            if (cx > T[jj + 2].FX) ax += E2.x;                            \
            if (cy > T[jj + 2].FY) ay += E2.y;                            \
            tx[jj] = ax; ty[jj] = ay;                                     \
        }                                                                 \
        _Pragma("unroll")                                                 \
        for (int j = 0; j < 5; j++) {                                     \
            if (M[j].FX > M[j + 1].FX) {                                  \
                if (j >= 1) tx[j - 1] += E7.x;                            \
            } else {                                                      \
                if (j <= 3) tx[j] += E3.x;                                \
            }                                                             \
            if (M[j].FY > M[j + 1].FY) {                                  \
                if (j >= 1) ty[j - 1] += E7.y;                            \
            } else {                                                      \
                if (j <= 3) ty[j] += E3.y;                                \
            }                                                             \
        }                                                                 \
    }

    // ROW1: shared middle edges (M<->C) finish row0 (l4,l5,l6) and start
    // row1 (l0,l1,l2 as complements); then row1 horizontals + bottom halo
    // vs D; masked stores for both rows of this channel pair.
    #define ROW1(M, C, D, FX, FY, ep, tx, ty, cA) {                       \
        const float2 E0 = ep[0], E1 = ep[1], E2 = ep[2], E3 = ep[3];      \
        const float2 E4 = ep[4], E5 = ep[5], E6 = ep[6], E7 = ep[7];      \
        float bx[4], by[4];                                               \
        _Pragma("unroll")                                                 \
        for (int k2 = 0; k2 < 4; k2++) { bx[k2] = 0.f; by[k2] = 0.f; }    \
        /* DL edges: M[a+1] vs C[a] -> row0 BL (l4), row1 TR (l2) */      \
        _Pragma("unroll")                                                 \
        for (int a = 0; a < 5; a++) {                                     \
            if (M[a + 1].FX > C[a].FX) {                                  \
                if (a <= 3) tx[a] += E4.x;                                \
            } else {                                                      \
                if (a >= 1) bx[a - 1] += E2.x;                            \
            }                                                             \
            if (M[a + 1].FY > C[a].FY) {                                  \
                if (a <= 3) ty[a] += E4.y;                                \
            } else {                                                      \
                if (a >= 1) by[a - 1] += E2.y;                            \
            }                                                             \
        }                                                                 \
        /* V edges: M[a+1] vs C[a+1] -> row0 B (l5), row1 T (l1) */       \
        _Pragma("unroll")                                                 \
        for (int a = 0; a < 4; a++) {                                     \
            if (M[a + 1].FX > C[a + 1].FX) tx[a] += E5.x;                 \
            else                           bx[a] += E1.x;                 \
            if (M[a + 1].FY > C[a + 1].FY) ty[a] += E5.y;                 \
            else                           by[a] += E1.y;                 \
        }                                                                 \
        /* DR edges: M[a] vs C[a+1] -> row0 BR (l6), row1 TL (l0) */      \
        _Pragma("unroll")                                                 \
        for (int a = 0; a < 5; a++) {                                     \
            if (M[a].FX > C[a + 1].FX) {                                  \
                if (a >= 1) tx[a - 1] += E6.x;                            \
            } else {                                                      \
                if (a <= 3) bx[a] += E0.x;                                \
            }                                                             \
            if (M[a].FY > C[a + 1].FY) {                                  \
                if (a >= 1) ty[a - 1] += E6.y;                            \
            } else {                                                      \
                if (a <= 3) by[a] += E0.y;                                \
            }                                                             \
        }                                                                 \
        /* row1 horizontal edges on C (l3, l7) */                         \
        _Pragma("unroll")                                                 \
        for (int j = 0; j < 5; j++) {                                     \
            if (C[j].FX > C[j + 1].FX) {                                  \
                if (j >= 1) bx[j - 1] += E7.x;                            \
            } else {                                                      \
                if (j <= 3) bx[j] += E3.x;                                \
            }                                                             \
            if (C[j].FY > C[j + 1].FY) {                                  \
                if (j >= 1) by[j - 1] += E7.y;                            \
            } else {                                                      \
                if (j <= 3) by[j] += E3.y;                                \
            }                                                             \
        }                                                                 \
        /* bottom halo: row1 l4,l5,l6 vs D */                             \
        _Pragma("unroll")                                                 \
        for (int jj = 0; jj < 4; jj++) {                                  \
            const float cx = C[jj + 1].FX, cy = C[jj + 1].FY;             \
            if (cx > D[jj    ].FX) bx[jj] += E4.x;                        \
            if (cy > D[jj    ].FY) by[jj] += E4.y;                        \
            if (cx > D[jj + 1].FX) bx[jj] += E5.x;                        \
            if (cy > D[jj + 1].FY) by[jj] += E5.y;                        \
            if (cx > D[jj + 2].FX) bx[jj] += E6.x;                        \
            if (cy > D[jj + 2].FY) by[jj] += E6.y;                        \
        }                                                                 \
        float* op0 = outB + (cA) * PLANE + oh0 * WW;                      \
        float* op1 = op0 + WW;                                            \
        *(float4*)op0 = make_float4(tx[0] * mk0[0], tx[1] * mk0[1],       \
                                    tx[2] * mk0[2], tx[3] * mk0[3]);      \
        *(float4*)(op0 + PLANE) = make_float4(                            \
            ty[0] * mk0[0], ty[1] * mk0[1],                               \
            ty[2] * mk0[2], ty[3] * mk0[3]);                              \
        *(float4*)op1 = make_float4(bx[0] * mk1[0], bx[1] * mk1[1],       \
                                    bx[2] * mk1[2], bx[3] * mk1[3]);      \
        *(float4*)(op1 + PLANE) = make_float4(                            \
            by[0] * mk1[0], by[1] * mk1[1],                               \
            by[2] * mk1[2], by[3] * mk1[3]);                              \
    }

    #pragma unroll
    for (int ch2 = 0; ch2 < 2; ch2++) {
        float4 (*cur)[CP] = sm->sy[ch2];

        float4 A[6], Bw[6], Cw[6];
        #pragma unroll
        for (int j = 0; j < 6; j++) {
            A[j]  = cur[hr0    ][sw(sc0 + j)];
            Bw[j] = cur[hr0 + 1][sw(sc0 + j)];
            Cw[j] = cur[hr0 + 2][sw(sc0 + j)];
        }

        float t1x[4], t1y[4], t2x[4], t2y[4];
        {
            const float2* ep = sm->sewp[2 * ch2];
            ROW0(A, Bw, x, y, ep, t1x, t1y)
        }
        {
            const float2* ep = sm->sewp[2 * ch2 + 1];
            ROW0(A, Bw, z, w, ep, t2x, t2y)
        }

        // roll: A now holds the row below row1 (D)
        #pragma unroll
        for (int j = 0; j < 6; j++)
            A[j] = cur[hr0 + 3][sw(sc0 + j)];

        {
            const float2* ep = sm->sewp[2 * ch2];
            ROW1(Bw, Cw, A, x, y, ep, t1x, t1y, 4 * ch2)
        }
        {
            const float2* ep = sm->sewp[2 * ch2 + 1];
            ROW1(Bw, Cw, A, z, w, ep, t2x, t2y, 4 * ch2 + 2)
        }
    }
    #undef ROW0
    #undef ROW1
}

extern "C" void kernel_launch(void* const* d_in, const int* in_sizes, int n_in,
                              void* d_out, int out_size)
{
    const float* x  = (const float*)d_in[0];
    const float* cw = (const float*)d_in[1];
    const float* w  = (const float*)d_in[2];
    float* out = (float*)d_out;

    const int smbytes = (int)sizeof(Sm);   // 80768
    cudaFuncSetAttribute(lbp_main, cudaFuncAttributeMaxDynamicSharedMemorySize,
                         smbytes);

    dim3 grid(WW / TW, HH / TH, NN * 8);   // (4, 8, 64) = 2048 blocks
    lbp_main<<<grid, NT, smbytes>>>(x, cw, w, out);
}